// round 1
// baseline (speedup 1.0000x reference)
#include <cuda_runtime.h>

// BoxLoss: YOLO-style box regression loss over 3 scales.
// Key insight: only <=50 cells per (image, scale) are ever "kept" (the ones a
// target gets scattered to), so we gather those cells instead of scanning the
// 88MB output tensors. Work is tiny -> launch-latency bound.

#define NT   50      // targets per image
#define NA   3       // anchors per scale
#define NC   85      // channels per cell
#define BMAX 32      // batch size (fixed by problem)
#define THRESH 0.5f

// per-(image,scale) partial losses; __device__ global = allowed scratch
__device__ float g_partials[BMAX * 3];

__global__ void box_loss_kernel(const float* __restrict__ out0,
                                const float* __restrict__ anc0,
                                const float* __restrict__ out1,
                                const float* __restrict__ anc1,
                                const float* __restrict__ out2,
                                const float* __restrict__ anc2,
                                const float* __restrict__ targets)
{
    const int b = blockIdx.x;     // image
    const int s = blockIdx.y;     // scale

    const float* out;
    const float* anc;
    int G;
    if      (s == 0) { out = out0; anc = anc0; G = 52; }
    else if (s == 1) { out = out1; anc = anc1; G = 26; }
    else             { out = out2; anc = anc2; G = 13; }

    __shared__ int   skey[NT];
    __shared__ float stx[NT], sty[NT], stw[NT], sth[NT];
    __shared__ float sanc[NA * 2];
    __shared__ float red_sum[2];
    __shared__ int   red_cnt[2];

    const int tid = threadIdx.x;

    if (tid < NA * 2) sanc[tid] = anc[tid];
    __syncthreads();

    // ---- phase 1: per-target anchor assignment ----
    if (tid < NT) {
        const float* tg = targets + ((size_t)b * NT + tid) * 5 + 1;
        const float x = tg[0], y = tg[1], w = tg[2], h = tg[3];
        const bool valid = !(x == 0.f && y == 0.f && w == 0.f && h == 0.f);

        const float fG = (float)G;
        const float tx = x * fG, ty = y * fG, tw = w * fG, th = h * fG;
        const float cx = floorf(tx), cy = floorf(ty);
        const float zx = tx - cx - 0.5f, zy = ty - cy - 0.5f;

        // target rect (match reference: areas computed from rect diffs)
        const float t0 = zx - tw * 0.5f, t1 = zy - th * 0.5f;
        const float t2 = zx + tw * 0.5f, t3 = zy + th * 0.5f;
        const float area_t = (t2 - t0) * (t3 - t1);

        float overlap = -1.f;
        int   best = 0;
        #pragma unroll
        for (int a = 0; a < NA; a++) {
            const float aw = sanc[a * 2], ah = sanc[a * 2 + 1];
            const float a0 = -aw * 0.5f, a1 = -ah * 0.5f;
            const float a2 =  aw * 0.5f, a3 =  ah * 0.5f;
            const float x0 = fmaxf(t0, a0), y0 = fmaxf(t1, a1);
            const float x1 = fminf(t2, a2), y1 = fminf(t3, a3);
            const float inter = (x0 < x1 && y0 < y1) ? (x1 - x0) * (y1 - y0) : 0.f;
            const float area_a = (a2 - a0) * (a3 - a1);
            const float iou = inter / (area_t + area_a - inter);
            if (iou > overlap) { overlap = iou; best = a; }   // first-max wins (strict >)
        }

        const int icx = (int)cx, icy = (int)cy;
        const bool assigned = valid && (overlap > THRESH) &&
                              icx >= 0 && icx < G && icy >= 0 && icy < G;
        skey[tid] = assigned ? (best * G + icy) * G + icx : -1;
        stx[tid] = tx; sty[tid] = ty; stw[tid] = tw; sth[tid] = th;
    }
    __syncthreads();

    // ---- phase 2: collision resolution (last target index wins) + gather ----
    float sum = 0.f;
    int   cnt = 0;
    if (tid < NT) {
        const int k = skey[tid];
        if (k >= 0) {
            bool win = true;
            for (int j = tid + 1; j < NT; j++)
                if (skey[j] == k) { win = false; break; }
            if (win) {
                const int anc_i = k / (G * G);
                const int cy_i  = (k / G) % G;
                const int cx_i  = k % G;
                const long long base =
                    ((((long long)b * NA + anc_i) * G + cy_i) * G + cx_i) * NC;
                const float px = out[base + 0], py = out[base + 1];
                const float pw = out[base + 2], ph = out[base + 3];
                const float dx = px - stx[tid];
                const float dy = py - sty[tid];
                const float rw = rsqrtf(pw) - rsqrtf(stw[tid]);
                const float rh = rsqrtf(ph) - rsqrtf(sth[tid]);
                sum = dx * dx + dy * dy + rw * rw + rh * rh;
                cnt = 1;
            }
        }
    }

    // ---- block reduce over 64 threads (2 warps) ----
    #pragma unroll
    for (int off = 16; off > 0; off >>= 1) {
        sum += __shfl_down_sync(0xffffffffu, sum, off);
        cnt += __shfl_down_sync(0xffffffffu, cnt, off);
    }
    if ((tid & 31) == 0) { red_sum[tid >> 5] = sum; red_cnt[tid >> 5] = cnt; }
    __syncthreads();
    if (tid == 0) {
        const float total = red_sum[0] + red_sum[1];
        const int   n     = red_cnt[0] + red_cnt[1];
        g_partials[b * 3 + s] = (n > 0) ? total / (2.0f * (float)n) : 0.f;
    }
}

__global__ void box_loss_reduce(float* __restrict__ out, int npart, float invB)
{
    // single thread, fixed order -> fully deterministic
    if (threadIdx.x == 0) {
        float s = 0.f;
        for (int i = 0; i < npart; i++) s += g_partials[i];
        out[0] = s * invB;
    }
}

extern "C" void kernel_launch(void* const* d_in, const int* in_sizes, int n_in,
                              void* d_out, int out_size)
{
    const float* out0 = (const float*)d_in[0];
    const float* anc0 = (const float*)d_in[1];
    const float* out1 = (const float*)d_in[2];
    const float* anc1 = (const float*)d_in[3];
    const float* out2 = (const float*)d_in[4];
    const float* anc2 = (const float*)d_in[5];
    const float* tgts = (const float*)d_in[6];

    int B = in_sizes[6] / (NT * 5);
    if (B > BMAX) B = BMAX;

    dim3 grid(B, 3);
    box_loss_kernel<<<grid, 64>>>(out0, anc0, out1, anc1, out2, anc2, tgts);
    box_loss_reduce<<<1, 32>>>((float*)d_out, B * 3, 1.0f / (float)B);
}

// round 2
// speedup vs baseline: 1.1404x; 1.1404x over previous
#include <cuda_runtime.h>

// BoxLoss: YOLO-style box regression loss over 3 scales, single fused launch.
// Only <=50 cells per (image, scale) are "kept" -> gather those cells instead
// of scanning the 88MB outputs. Work is tiny: the kernel is launch/latency
// bound, so everything (96 tasks + final reduce) happens in ONE launch using
// the last-block-done pattern.

#define NT   50      // targets per image
#define NA   3       // anchors per scale
#define NC   85      // channels per cell
#define BMAX 32      // batch size cap
#define THRESH 0.5f

__device__ float        g_partials[BMAX * 3];
__device__ unsigned int g_done = 0;

__global__ void box_loss_fused(const float* __restrict__ out0,
                               const float* __restrict__ anc0,
                               const float* __restrict__ out1,
                               const float* __restrict__ anc1,
                               const float* __restrict__ out2,
                               const float* __restrict__ anc2,
                               const float* __restrict__ targets,
                               float* __restrict__ result,
                               int nparts, float invB)
{
    const int b = blockIdx.x;     // image
    const int s = blockIdx.y;     // scale

    const float* out;
    const float* anc;
    int G;
    if      (s == 0) { out = out0; anc = anc0; G = 52; }
    else if (s == 1) { out = out1; anc = anc1; G = 26; }
    else             { out = out2; anc = anc2; G = 13; }

    __shared__ int   skey[NT];
    __shared__ float red_sum[2];
    __shared__ int   red_cnt[2];
    __shared__ float sanc[NA * 2];
    __shared__ int   s_last;

    const int tid = threadIdx.x;

    if (tid < NA * 2) sanc[tid] = anc[tid];
    __syncthreads();

    // ---- phase 1: per-target anchor assignment ----
    float tx = 0.f, ty = 0.f, tw = 1.f, th = 1.f;
    if (tid < NT) {
        const float* tg = targets + ((size_t)b * NT + tid) * 5 + 1;
        const float x = tg[0], y = tg[1], w = tg[2], h = tg[3];
        const bool valid = !(x == 0.f && y == 0.f && w == 0.f && h == 0.f);

        const float fG = (float)G;
        tx = x * fG; ty = y * fG; tw = w * fG; th = h * fG;
        const float cx = floorf(tx), cy = floorf(ty);
        const float zx = tx - cx - 0.5f, zy = ty - cy - 0.5f;

        // target rect (areas from rect diffs, matching the reference exactly)
        const float t0 = zx - tw * 0.5f, t1 = zy - th * 0.5f;
        const float t2 = zx + tw * 0.5f, t3 = zy + th * 0.5f;
        const float area_t = (t2 - t0) * (t3 - t1);

        float overlap = -1.f;
        int   best = 0;
        #pragma unroll
        for (int a = 0; a < NA; a++) {
            const float aw = sanc[a * 2], ah = sanc[a * 2 + 1];
            const float a0 = -aw * 0.5f, a1 = -ah * 0.5f;
            const float a2 =  aw * 0.5f, a3 =  ah * 0.5f;
            const float x0 = fmaxf(t0, a0), y0 = fmaxf(t1, a1);
            const float x1 = fminf(t2, a2), y1 = fminf(t3, a3);
            const float inter = (x0 < x1 && y0 < y1) ? (x1 - x0) * (y1 - y0) : 0.f;
            const float area_a = (a2 - a0) * (a3 - a1);
            const float iou = inter / (area_t + area_a - inter);
            if (iou > overlap) { overlap = iou; best = a; }   // first-max wins
        }

        const int icx = (int)cx, icy = (int)cy;
        const bool assigned = valid && (overlap > THRESH) &&
                              icx >= 0 && icx < G && icy >= 0 && icy < G;
        skey[tid] = assigned ? (best * G + icy) * G + icx : -1;
    } else if (tid < 64) {
        // nothing
    }
    __syncthreads();

    // ---- phase 2: collision resolution (last target index wins) + gather ----
    float sum = 0.f;
    int   cnt = 0;
    if (tid < NT) {
        const int k = skey[tid];
        if (k >= 0) {
            bool win = true;
            for (int j = tid + 1; j < NT; j++)
                if (skey[j] == k) { win = false; break; }
            if (win) {
                const int anc_i = k / (G * G);
                const int cy_i  = (k / G) % G;
                const int cx_i  = k % G;
                const long long base =
                    ((((long long)b * NA + anc_i) * G + cy_i) * G + cx_i) * NC;
                const float px = out[base + 0], py = out[base + 1];
                const float pw = out[base + 2], ph = out[base + 3];
                const float dx = px - tx;
                const float dy = py - ty;
                const float rw = rsqrtf(pw) - rsqrtf(tw);
                const float rh = rsqrtf(ph) - rsqrtf(th);
                sum = dx * dx + dy * dy + rw * rw + rh * rh;
                cnt = 1;
            }
        }
    }

    // ---- block reduce over 64 threads (2 warps) ----
    #pragma unroll
    for (int off = 16; off > 0; off >>= 1) {
        sum += __shfl_down_sync(0xffffffffu, sum, off);
        cnt += __shfl_down_sync(0xffffffffu, cnt, off);
    }
    if ((tid & 31) == 0) { red_sum[tid >> 5] = sum; red_cnt[tid >> 5] = cnt; }
    __syncthreads();

    // ---- publish partial + last-block-done detection ----
    if (tid == 0) {
        const float total = red_sum[0] + red_sum[1];
        const int   n     = red_cnt[0] + red_cnt[1];
        g_partials[b * 3 + s] = (n > 0) ? total / (2.0f * (float)n) : 0.f;
        __threadfence();                                   // make partial visible
        unsigned int prev = atomicAdd(&g_done, 1u);
        s_last = (prev == (unsigned int)(nparts - 1)) ? 1 : 0;
    }
    __syncthreads();

    // ---- final reduce, done by whichever block finished last ----
    if (s_last) {
        __threadfence();   // acquire: order after the counter observation
        float v = 0.f;
        if (tid < nparts)      v  = __ldcg(&g_partials[tid]);
        if (tid + 64 < nparts) v += __ldcg(&g_partials[tid + 64]);
        #pragma unroll
        for (int off = 16; off > 0; off >>= 1)
            v += __shfl_down_sync(0xffffffffu, v, off);
        if ((tid & 31) == 0) red_sum[tid >> 5] = v;
        __syncthreads();
        if (tid == 0) {
            result[0] = (red_sum[0] + red_sum[1]) * invB;
            g_done = 0;                      // reset for next graph replay
        }
    }
}

extern "C" void kernel_launch(void* const* d_in, const int* in_sizes, int n_in,
                              void* d_out, int out_size)
{
    const float* out0 = (const float*)d_in[0];
    const float* anc0 = (const float*)d_in[1];
    const float* out1 = (const float*)d_in[2];
    const float* anc1 = (const float*)d_in[3];
    const float* out2 = (const float*)d_in[4];
    const float* anc2 = (const float*)d_in[5];
    const float* tgts = (const float*)d_in[6];

    int B = in_sizes[6] / (NT * 5);
    if (B > BMAX) B = BMAX;

    dim3 grid(B, 3);
    box_loss_fused<<<grid, 64>>>(out0, anc0, out1, anc1, out2, anc2, tgts,
                                 (float*)d_out, B * 3, 1.0f / (float)B);
}

// round 3
// speedup vs baseline: 1.4466x; 1.2685x over previous
#include <cuda_runtime.h>

// BoxLoss: YOLO-style box loss, 3 scales, ONE launch, 32 blocks (1 per image).
// Latency-bound at idle DVFS clocks -> minimize serial-chain cycles:
//  - all global loads issued up front (targets once per image, 3 anchor sets)
//  - speculative gather issued before dup-check (DRAM latency overlaps sync)
//  - per-image scale fusion in shared memory; only 32-wide global tail

#define NT   50      // targets per image
#define NA   3       // anchors per scale
#define NC   85      // channels per cell
#define BMAX 32
#define THRESH 0.5f

__device__ float        g_partials[BMAX];
__device__ unsigned int g_done = 0;

__global__ void __launch_bounds__(192, 1)
box_loss_fused(const float* __restrict__ out0,
               const float* __restrict__ anc0,
               const float* __restrict__ out1,
               const float* __restrict__ anc1,
               const float* __restrict__ out2,
               const float* __restrict__ anc2,
               const float* __restrict__ targets,
               float* __restrict__ result,
               int B, float invB)
{
    const int b   = blockIdx.x;
    const int tid = threadIdx.x;
    const int g   = tid >> 6;     // scale group 0..2 (64 threads each)
    const int l   = tid & 63;     // lane within group

    __shared__ float sraw[NT * 5];
    __shared__ float sanc[3][6];
    __shared__ int   skey[3][64];
    __shared__ float wsum[6];
    __shared__ int   wcnt[6];
    __shared__ int   s_last;

    // ---- front-load ALL global reads (one DRAM round trip, overlapped) ----
    #pragma unroll
    for (int i = tid; i < NT * 5; i += 192)
        sraw[i] = targets[(size_t)b * NT * 5 + i];
    if (tid < 6)       sanc[0][tid]      = anc0[tid];
    else if (tid < 12) sanc[1][tid - 6]  = anc1[tid - 6];
    else if (tid < 18) sanc[2][tid - 12] = anc2[tid - 12];
    __syncthreads();

    const float* out = (g == 0) ? out0 : (g == 1) ? out1 : out2;
    const int    G   = (g == 0) ? 52   : (g == 1) ? 26   : 13;

    // ---- phase 1: per-target anchor assignment ----
    int   key = -1;
    int   best = 0, icx = 0, icy = 0;
    float tx = 0.f, ty = 0.f, tw = 1.f, th = 1.f;
    if (l < NT) {
        const float x = sraw[l * 5 + 1], y = sraw[l * 5 + 2];
        const float w = sraw[l * 5 + 3], h = sraw[l * 5 + 4];
        const bool valid = !(x == 0.f && y == 0.f && w == 0.f && h == 0.f);

        const float fG = (float)G;
        tx = x * fG; ty = y * fG; tw = w * fG; th = h * fG;
        const float cx = floorf(tx), cy = floorf(ty);
        const float zx = tx - cx - 0.5f, zy = ty - cy - 0.5f;

        // target rect; areas from rect diffs (matches reference numerics)
        const float t0 = zx - tw * 0.5f, t1 = zy - th * 0.5f;
        const float t2 = zx + tw * 0.5f, t3 = zy + th * 0.5f;
        const float area_t = (t2 - t0) * (t3 - t1);

        float overlap = -1.f;
        #pragma unroll
        for (int a = 0; a < NA; a++) {
            const float aw = sanc[g][a * 2], ah = sanc[g][a * 2 + 1];
            const float a0 = -aw * 0.5f, a1 = -ah * 0.5f;
            const float a2 =  aw * 0.5f, a3 =  ah * 0.5f;
            const float x0 = fmaxf(t0, a0), y0 = fmaxf(t1, a1);
            const float x1 = fminf(t2, a2), y1 = fminf(t3, a3);
            const float inter = (x0 < x1 && y0 < y1) ? (x1 - x0) * (y1 - y0) : 0.f;
            const float area_a = (a2 - a0) * (a3 - a1);
            const float iou = inter / (area_t + area_a - inter);
            if (iou > overlap) { overlap = iou; best = a; }  // first-max wins
        }

        icx = (int)cx; icy = (int)cy;
        if (valid && overlap > THRESH && icx >= 0 && icx < G && icy >= 0 && icy < G)
            key = (best * G + icy) * G + icx;
    }
    skey[g][l] = key;

    // ---- speculative gather: address depends only on OWN key; issue the
    //      loads now so DRAM latency overlaps the sync + dup-check ----
    float px = 0.f, py = 0.f, pw = 1.f, ph = 1.f;
    if (key >= 0) {
        const float* c = out +
            ((((long long)b * NA + best) * G + icy) * G + icx) * (long long)NC;
        px = __ldg(c + 0); py = __ldg(c + 1);
        pw = __ldg(c + 2); ph = __ldg(c + 3);
    }
    __syncthreads();

    // ---- phase 2: collision resolution (last target index wins) ----
    float sum = 0.f;
    int   cnt = 0;
    if (key >= 0) {
        bool win = true;
        for (int j = l + 1; j < NT; j++)
            if (skey[g][j] == key) { win = false; break; }
        if (win) {
            const float dx = px - tx;
            const float dy = py - ty;
            const float rw = rsqrtf(pw) - rsqrtf(tw);
            const float rh = rsqrtf(ph) - rsqrtf(th);
            sum = dx * dx + dy * dy + rw * rw + rh * rh;
            cnt = 1;
        }
    }

    // ---- warp reduce (6 full warps), then per-image combine in shared ----
    #pragma unroll
    for (int off = 16; off > 0; off >>= 1) {
        sum += __shfl_down_sync(0xffffffffu, sum, off);
        cnt += __shfl_down_sync(0xffffffffu, cnt, off);
    }
    const int wid = tid >> 5;
    if ((tid & 31) == 0) { wsum[wid] = sum; wcnt[wid] = cnt; }
    __syncthreads();

    if (tid == 0) {
        float p = 0.f;
        #pragma unroll
        for (int gg = 0; gg < 3; gg++) {
            const float t = wsum[2 * gg] + wsum[2 * gg + 1];
            const int   n = wcnt[2 * gg] + wcnt[2 * gg + 1];
            if (n > 0) p += t / (2.0f * (float)n);
        }
        g_partials[b] = p;
        __threadfence();
        unsigned prev = atomicAdd(&g_done, 1u);
        s_last = (prev == (unsigned)(B - 1)) ? 1 : 0;
    }
    __syncthreads();

    // ---- final reduce by the last-arriving block (deterministic order) ----
    if (s_last && tid < 32) {
        __threadfence();
        float v = (tid < B) ? __ldcg(&g_partials[tid]) : 0.f;
        #pragma unroll
        for (int off = 16; off > 0; off >>= 1)
            v += __shfl_down_sync(0xffffffffu, v, off);
        if (tid == 0) {
            result[0] = v * invB;
            g_done = 0;                  // reset for next graph replay
        }
    }
}

extern "C" void kernel_launch(void* const* d_in, const int* in_sizes, int n_in,
                              void* d_out, int out_size)
{
    const float* out0 = (const float*)d_in[0];
    const float* anc0 = (const float*)d_in[1];
    const float* out1 = (const float*)d_in[2];
    const float* anc1 = (const float*)d_in[3];
    const float* out2 = (const float*)d_in[4];
    const float* anc2 = (const float*)d_in[5];
    const float* tgts = (const float*)d_in[6];

    int B = in_sizes[6] / (NT * 5);
    if (B > BMAX) B = BMAX;

    box_loss_fused<<<B, 192>>>(out0, anc0, out1, anc1, out2, anc2, tgts,
                               (float*)d_out, B, 1.0f / (float)B);
}

// round 4
// speedup vs baseline: 1.5761x; 1.0896x over previous
#include <cuda_runtime.h>

// BoxLoss: YOLO-style box loss, 3 scales, ONE launch, 32 blocks (1 per image).
// Latency-bound -> minimize serial-chain cycles:
//  - every global load (targets, anchors) issued before any compute
//  - gather issued speculatively for ALL 3 anchors right after floor(cx,cy),
//    overlapping the IoU loop + sync + dup-check
//  - NO atomics / NO fences in the tail: the partial value (always >= 0) is
//    its own readiness flag (sentinel = -1.0f); block 0 polls L2 and reduces
//    in fixed lane order (deterministic), then resets sentinels for replay.

#define NT   50      // targets per image
#define NA   3       // anchors per scale
#define NC   85      // channels per cell
#define BMAX 32
#define THRESH 0.5f

#define M1 -1.f,-1.f,-1.f,-1.f,-1.f,-1.f,-1.f,-1.f
__device__ float g_partials[BMAX] = { M1, M1, M1, M1 };

__device__ __forceinline__ float ld_cg(const float* p) {
    float v;
    asm volatile("ld.global.cg.f32 %0, [%1];" : "=f"(v) : "l"(p) : "memory");
    return v;
}
__device__ __forceinline__ void st_cg(float* p, float v) {
    asm volatile("st.global.cg.f32 [%0], %1;" :: "l"(p), "f"(v) : "memory");
}

__global__ void __launch_bounds__(192, 1)
box_loss_fused(const float* __restrict__ out0,
               const float* __restrict__ anc0,
               const float* __restrict__ out1,
               const float* __restrict__ anc1,
               const float* __restrict__ out2,
               const float* __restrict__ anc2,
               const float* __restrict__ targets,
               float* __restrict__ result,
               float invB)
{
    const int b   = blockIdx.x;
    const int B   = gridDim.x;
    const int tid = threadIdx.x;
    const int g   = tid >> 6;     // scale group 0..2 (64 lanes each)
    const int l   = tid & 63;

    __shared__ int   skey[3][64];
    __shared__ float wsum[6];
    __shared__ int   wcnt[6];

    const float* out = (g == 0) ? out0 : (g == 1) ? out1 : out2;
    const float* anc = (g == 0) ? anc0 : (g == 1) ? anc1 : anc2;
    const int    G   = (g == 0) ? 52   : (g == 1) ? 26   : 13;

    // ---- issue ALL independent global loads up front ----
    float aw0 = __ldg(anc + 0), ah0 = __ldg(anc + 1);
    float aw1 = __ldg(anc + 2), ah1 = __ldg(anc + 3);
    float aw2 = __ldg(anc + 4), ah2 = __ldg(anc + 5);

    float x = 0.f, y = 0.f, w = 0.f, h = 0.f;
    if (l < NT) {
        const float* tg = targets + ((size_t)b * NT + l) * 5;
        x = __ldg(tg + 1); y = __ldg(tg + 2);
        w = __ldg(tg + 3); h = __ldg(tg + 4);
    }

    // ---- scale + cell (only target load needed so far) ----
    const bool  valid = (l < NT) && !(x == 0.f && y == 0.f && w == 0.f && h == 0.f);
    const float fG = (float)G;
    const float tx = x * fG, ty = y * fG, tw = w * fG, th = h * fG;
    const float cx = floorf(tx), cy = floorf(ty);
    const int   icx = (int)cx,   icy = (int)cy;
    const bool  inb = valid && icx >= 0 && icx < G && icy >= 0 && icy < G;

    // ---- speculative gather for ALL 3 anchors (address independent of IoU);
    //      latency overlaps the IoU loop + sync + dup-check ----
    float px[NA], py[NA], pw[NA], ph[NA];
    #pragma unroll
    for (int a = 0; a < NA; a++) { px[a] = 0.f; py[a] = 0.f; pw[a] = 1.f; ph[a] = 1.f; }
    if (inb) {
        const long long cell = (((long long)b * NA) * G + icy) * G + icx;
        #pragma unroll
        for (int a = 0; a < NA; a++) {
            const float* c = out + (cell + (long long)a * G * G) * NC;
            px[a] = __ldg(c + 0); py[a] = __ldg(c + 1);
            pw[a] = __ldg(c + 2); ph[a] = __ldg(c + 3);
        }
    }

    // ---- IoU vs 3 anchors (areas from rect diffs, matching reference) ----
    const float zx = tx - cx - 0.5f, zy = ty - cy - 0.5f;
    const float t0 = zx - tw * 0.5f, t1 = zy - th * 0.5f;
    const float t2 = zx + tw * 0.5f, t3 = zy + th * 0.5f;
    const float area_t = (t2 - t0) * (t3 - t1);

    float overlap = -1.f;
    int   best = 0;
    #pragma unroll
    for (int a = 0; a < NA; a++) {
        const float aw = (a == 0) ? aw0 : (a == 1) ? aw1 : aw2;
        const float ah = (a == 0) ? ah0 : (a == 1) ? ah1 : ah2;
        const float a0 = -aw * 0.5f, a1 = -ah * 0.5f;
        const float a2 =  aw * 0.5f, a3 =  ah * 0.5f;
        const float x0 = fmaxf(t0, a0), y0 = fmaxf(t1, a1);
        const float x1 = fminf(t2, a2), y1 = fminf(t3, a3);
        const float inter = (x0 < x1 && y0 < y1) ? (x1 - x0) * (y1 - y0) : 0.f;
        const float area_a = (a2 - a0) * (a3 - a1);
        const float iou = inter / (area_t + area_a - inter);
        if (iou > overlap) { overlap = iou; best = a; }  // first-max wins
    }

    const int key = (inb && overlap > THRESH) ? (best * G + icy) * G + icx : -1;
    skey[g][l] = key;
    __syncthreads();

    // ---- collision resolution: last target index wins ----
    float sum = 0.f;
    int   cnt = 0;
    if (key >= 0) {
        bool win = true;
        for (int j = l + 1; j < NT; j++)
            if (skey[g][j] == key) { win = false; break; }
        if (win) {
            const float dx = px[best] - tx;
            const float dy = py[best] - ty;
            const float rw = rsqrtf(pw[best]) - rsqrtf(tw);
            const float rh = rsqrtf(ph[best]) - rsqrtf(th);
            sum = dx * dx + dy * dy + rw * rw + rh * rh;
            cnt = 1;
        }
    }

    // ---- reduce: shfl for float, REDUX for count ----
    #pragma unroll
    for (int off = 16; off > 0; off >>= 1)
        sum += __shfl_down_sync(0xffffffffu, sum, off);
    cnt = __reduce_add_sync(0xffffffffu, cnt);

    const int wid = tid >> 5;
    if ((tid & 31) == 0) { wsum[wid] = sum; wcnt[wid] = cnt; }
    __syncthreads();

    // ---- publish partial: value doubles as readiness flag (>= 0) ----
    if (tid == 0) {
        float p = 0.f;
        #pragma unroll
        for (int gg = 0; gg < 3; gg++) {
            const float t = wsum[2 * gg] + wsum[2 * gg + 1];
            const int   n = wcnt[2 * gg] + wcnt[2 * gg + 1];
            if (n > 0) p += t / (2.0f * (float)n);
        }
        st_cg(&g_partials[b], p);
    }

    // ---- block 0, warp 0: poll L2 until all partials published, reduce ----
    if (b == 0 && tid < 32) {
        const bool mine = (tid < B);
        float v = 0.f;
        for (;;) {
            if (mine) v = ld_cg(&g_partials[tid]);
            // sentinel is exact bit pattern of -1.0f; NaN-safe compare
            const bool pending = mine && (__float_as_uint(v) == 0xBF800000u);
            if (!__any_sync(0xffffffffu, pending)) break;
        }
        float s = mine ? v : 0.f;
        #pragma unroll
        for (int off = 16; off > 0; off >>= 1)
            s += __shfl_down_sync(0xffffffffu, s, off);
        if (mine) st_cg(&g_partials[tid], -1.0f);   // reset for next replay
        if (tid == 0) result[0] = s * invB;
    }
}

extern "C" void kernel_launch(void* const* d_in, const int* in_sizes, int n_in,
                              void* d_out, int out_size)
{
    const float* out0 = (const float*)d_in[0];
    const float* anc0 = (const float*)d_in[1];
    const float* out1 = (const float*)d_in[2];
    const float* anc1 = (const float*)d_in[3];
    const float* out2 = (const float*)d_in[4];
    const float* anc2 = (const float*)d_in[5];
    const float* tgts = (const float*)d_in[6];

    int B = in_sizes[6] / (NT * 5);
    if (B > BMAX) B = BMAX;

    box_loss_fused<<<B, 192>>>(out0, anc0, out1, anc1, out2, anc2, tgts,
                               (float*)d_out, 1.0f / (float)B);
}